// round 1
// baseline (speedup 1.0000x reference)
#include <cuda_runtime.h>
#include <cuda_bf16.h>
#include <math.h>

// ---------------------------------------------------------------------------
// GPT_3959959847300 baseline: fp32 everywhere, generic tiled GEMM.
// B=2, T=1024, C=512, H=8, L=4, V=50257, R=8, lora scale = 4.0
// ---------------------------------------------------------------------------

#define BSZ   2
#define TLEN  1024
#define CDIM  512
#define NHEAD 8
#define HD    64
#define NLAYER 4
#define VOCAB 50257
#define RANK  8
#define LSCALE 4.0f
#define MTOK  (BSZ*TLEN)          // 2048 token rows

// ------------------------- scratch (device globals) -------------------------
__device__ float g_X  [MTOK*CDIM];          // residual stream
__device__ float g_H  [MTOK*CDIM];          // layernorm output / misc
__device__ float g_QKV[MTOK*3*CDIM];        // qkv projection
__device__ float g_Q  [BSZ*NHEAD*TLEN*HD];  // per-head Q; reused as attn output
__device__ float g_K  [BSZ*NHEAD*TLEN*HD];
__device__ float g_V  [BSZ*NHEAD*TLEN*HD];
__device__ float g_ATT[BSZ*NHEAD*TLEN*TLEN]; // 64 MB attention matrix
__device__ float g_Y  [MTOK*CDIM];
__device__ float g_FC [MTOK*4*CDIM];        // 16 MB
__device__ float g_TMP[MTOK*RANK];          // lora x@A^T
__device__ int   g_idx32;                   // 1 if idx stored as int32

// ------------------------- idx dtype detection ------------------------------
__global__ void detect_idx_kernel(const unsigned int* w) {
    // If idx is int64, words at odd positions (high halves) are all zero
    // for positive tokens < 2^31. If int32, odd words are tokens (nonzero
    // with overwhelming probability over 1024 samples).
    __shared__ unsigned int s;
    if (threadIdx.x == 0) s = 0u;
    __syncthreads();
    unsigned int v = 0u;
    for (int i = threadIdx.x; i < 1024; i += blockDim.x) v |= w[2*i + 1];
    atomicOr(&s, v);
    __syncthreads();
    if (threadIdx.x == 0) g_idx32 = (s != 0u) ? 1 : 0;
}

// ------------------------- embedding ----------------------------------------
__global__ void embed_kernel(const void* idx, const float* __restrict__ wte,
                             const float* __restrict__ wpe, float* __restrict__ x) {
    int i = blockIdx.x * blockDim.x + threadIdx.x;
    if (i >= MTOK*CDIM) return;
    int c  = i % CDIM;
    int bt = i / CDIM;
    int t  = bt % TLEN;
    long long tok;
    if (g_idx32) tok = (long long)((const int*)idx)[bt];
    else         tok = ((const long long*)idx)[bt];
    x[i] = wte[tok*CDIM + c] + wpe[(long long)t*CDIM + c];
}

// ------------------------- layernorm (row = 512) -----------------------------
__global__ void ln_kernel(const float* __restrict__ x, const float* __restrict__ g,
                          const float* __restrict__ b, float* __restrict__ out) {
    const int row = blockIdx.x;
    const float* xr = x + (long long)row * CDIM;
    __shared__ float sx[CDIM];
    __shared__ float red[128];
    __shared__ float s_mean, s_rstd;
    int tid = threadIdx.x;                    // block 128
    float s = 0.f;
    for (int c = tid; c < CDIM; c += 128) { float v = xr[c]; sx[c] = v; s += v; }
    red[tid] = s; __syncthreads();
    for (int st = 64; st > 0; st >>= 1) { if (tid < st) red[tid] += red[tid+st]; __syncthreads(); }
    if (tid == 0) s_mean = red[0] / (float)CDIM;
    __syncthreads();
    float mean = s_mean;
    float sq = 0.f;
    for (int c = tid; c < CDIM; c += 128) { float d = sx[c] - mean; sq += d*d; }
    red[tid] = sq; __syncthreads();
    for (int st = 64; st > 0; st >>= 1) { if (tid < st) red[tid] += red[tid+st]; __syncthreads(); }
    if (tid == 0) s_rstd = rsqrtf(red[0] / (float)CDIM + 1e-5f);
    __syncthreads();
    float rstd = s_rstd;
    for (int c = tid; c < CDIM; c += 128)
        out[(long long)row*CDIM + c] = (sx[c] - mean) * rstd * g[c] + b[c];
}

// ------------------------- generic tiled GEMM --------------------------------
// C[M,N] = alpha * A[M,K] @ op(B) (+ bias[n]), batched via blockIdx.z.
// BT_MODE=1: B is [N,K] (multiply by B^T). BT_MODE=0: B is [K,N].
template<int BT_MODE>
__global__ __launch_bounds__(256, 2)
void gemm_kernel(const float* __restrict__ A, const float* __restrict__ Bm,
                 const float* __restrict__ bias, float* __restrict__ Cm,
                 int M, int N, int K, float alpha,
                 long long sA, long long sB, long long sC, int causal) {
    const int BM = 128, BN = 128, BK = 8;
    int bz = blockIdx.z;
    const float* Ab = A  + (long long)bz * sA;
    const float* Bb = Bm + (long long)bz * sB;
    float*       Cb = Cm + (long long)bz * sC;
    int m0 = blockIdx.y * BM;
    int n0 = blockIdx.x * BN;
    if (causal && n0 > m0 + BM - 1) return;   // fully-masked score block

    __shared__ float As[BK][BM];
    __shared__ float Bs[BK][BN];
    int tid = threadIdx.x;
    int tx = tid % 16, ty = tid / 16;
    float acc[8][8];
    #pragma unroll
    for (int i = 0; i < 8; i++)
        #pragma unroll
        for (int j = 0; j < 8; j++) acc[i][j] = 0.f;

    int a_m = tid >> 1;            // 0..127
    int a_k = (tid & 1) * 4;       // 0 or 4

    for (int k0 = 0; k0 < K; k0 += BK) {
        // --- load A tile (BM x BK) ---
        {
            int gm = m0 + a_m;
            const float* ap = Ab + (long long)gm * K + k0 + a_k;
            #pragma unroll
            for (int j = 0; j < 4; j++) {
                int gk = k0 + a_k + j;
                As[a_k + j][a_m] = (gm < M && gk < K) ? ap[j] : 0.f;
            }
        }
        // --- load B tile ---
        if (BT_MODE) {
            int gn = n0 + a_m;
            const float* bp = Bb + (long long)gn * K + k0 + a_k;
            #pragma unroll
            for (int j = 0; j < 4; j++) {
                int gk = k0 + a_k + j;
                Bs[a_k + j][a_m] = (gn < N && gk < K) ? bp[j] : 0.f;
            }
        } else {
            int lk = tid >> 5;            // 0..7
            int ln = (tid & 31) * 4;      // 0..124
            int gk = k0 + lk;
            const float* bp = Bb + (long long)gk * N + n0 + ln;
            #pragma unroll
            for (int j = 0; j < 4; j++) {
                int gn = n0 + ln + j;
                Bs[lk][ln + j] = (gk < K && gn < N) ? bp[j] : 0.f;
            }
        }
        __syncthreads();
        #pragma unroll
        for (int kk = 0; kk < BK; kk++) {
            float ra[8], rb[8];
            #pragma unroll
            for (int i = 0; i < 8; i++) ra[i] = As[kk][ty*8 + i];
            #pragma unroll
            for (int j = 0; j < 8; j++) rb[j] = Bs[kk][tx*8 + j];
            #pragma unroll
            for (int i = 0; i < 8; i++)
                #pragma unroll
                for (int j = 0; j < 8; j++)
                    acc[i][j] += ra[i] * rb[j];
        }
        __syncthreads();
    }

    #pragma unroll
    for (int i = 0; i < 8; i++) {
        int gm = m0 + ty*8 + i;
        if (gm >= M) continue;
        #pragma unroll
        for (int j = 0; j < 8; j++) {
            int gn = n0 + tx*8 + j;
            if (gn >= N) continue;
            float v = alpha * acc[i][j];
            if (bias) v += bias[gn];
            Cb[(long long)gm * N + gn] = v;
        }
    }
}

// ------------------------- LoRA ----------------------------------------------
__global__ void lora_xa_kernel(const float* __restrict__ h, const float* __restrict__ A,
                               float* __restrict__ tmp) {
    int m = blockIdx.x;                  // token row
    int w = threadIdx.x >> 5;            // warp -> rank index (8 warps)
    int lane = threadIdx.x & 31;
    const float* hr = h + (long long)m * CDIM;
    const float* Ar = A + (long long)w * CDIM;
    float s = 0.f;
    for (int c = lane; c < CDIM; c += 32) s += hr[c] * Ar[c];
    #pragma unroll
    for (int o = 16; o > 0; o >>= 1) s += __shfl_down_sync(0xffffffffu, s, o);
    if (lane == 0) tmp[m*RANK + w] = s;
}

__global__ void lora_add_kernel(float* __restrict__ out, const float* __restrict__ tmp,
                                const float* __restrict__ Bm, int N) {
    long long i = (long long)blockIdx.x * 256 + threadIdx.x;
    if (i >= (long long)MTOK * N) return;
    int n = (int)(i % N);
    int m = (int)(i / N);
    const float* t = tmp + m*RANK;
    const float* b = Bm + (long long)n*RANK;
    float s = 0.f;
    #pragma unroll
    for (int r = 0; r < RANK; r++) s += t[r] * b[r];
    out[i] += LSCALE * s;
}

// ------------------------- attention plumbing ---------------------------------
__global__ void split_qkv_kernel(const float* __restrict__ qkv, float* __restrict__ q,
                                 float* __restrict__ k, float* __restrict__ v) {
    int i = blockIdx.x * 256 + threadIdx.x;   // over B*H*T*HD
    if (i >= BSZ*NHEAD*TLEN*HD) return;
    int d = i % HD;
    int t = (i / HD) % TLEN;
    int h = (i / (HD*TLEN)) % NHEAD;
    int b = i / (HD*TLEN*NHEAD);
    long long src = ((long long)(b*TLEN + t)) * (3*CDIM) + h*HD + d;
    q[i] = qkv[src];
    k[i] = qkv[src + CDIM];
    v[i] = qkv[src + 2*CDIM];
}

__global__ void merge_y_kernel(const float* __restrict__ yh, float* __restrict__ y) {
    int i = blockIdx.x * 256 + threadIdx.x;   // over B*T*C
    if (i >= MTOK*CDIM) return;
    int c = i % CDIM;
    int t = (i / CDIM) % TLEN;
    int b = i / (CDIM*TLEN);
    int h = c / HD, d = c % HD;
    y[i] = yh[(((long long)(b*NHEAD + h) * TLEN) + t) * HD + d];
}

__global__ void softmax_kernel(float* __restrict__ att) {
    int row = blockIdx.x;                 // bh*T + q
    int q = row % TLEN;
    float* a = att + (long long)row * TLEN;
    int tid = threadIdx.x;                // block 256
    __shared__ float red[256];
    float mx = -1e30f;
    for (int k = tid; k <= q; k += 256) mx = fmaxf(mx, a[k]);
    red[tid] = mx; __syncthreads();
    for (int s = 128; s > 0; s >>= 1) { if (tid < s) red[tid] = fmaxf(red[tid], red[tid+s]); __syncthreads(); }
    mx = red[0];
    __syncthreads();
    float sum = 0.f;
    for (int k = tid; k <= q; k += 256) { float e = expf(a[k] - mx); a[k] = e; sum += e; }
    red[tid] = sum; __syncthreads();
    for (int s = 128; s > 0; s >>= 1) { if (tid < s) red[tid] += red[tid+s]; __syncthreads(); }
    float inv = 1.f / red[0];
    for (int k = tid; k <= q; k += 256) a[k] *= inv;
    for (int k = q + 1 + tid; k < TLEN; k += 256) a[k] = 0.f;   // zero masked tail
}

// ------------------------- elementwise ----------------------------------------
__global__ void add_kernel(float* __restrict__ x, const float* __restrict__ y, int n) {
    int i = blockIdx.x * 256 + threadIdx.x;
    if (i < n) x[i] += y[i];
}

__global__ void gelu_kernel(float* __restrict__ x, int n) {
    int i = blockIdx.x * 256 + threadIdx.x;
    if (i >= n) return;
    float v = x[i];
    x[i] = 0.5f * v * (1.f + tanhf(0.7978845608028654f * (v + 0.044715f * v*v*v)));
}

// ------------------------- host driver -----------------------------------------
static inline dim3 gemm_grid(int M, int N, int batch) {
    return dim3((N + 127) / 128, (M + 127) / 128, batch);
}

extern "C" void kernel_launch(void* const* d_in, const int* in_sizes, int n_in,
                              void* d_out, int out_size) {
    (void)in_sizes; (void)n_in; (void)out_size;
    const void*  idx     = d_in[0];
    const float* wte     = (const float*)d_in[1];
    const float* wpe     = (const float*)d_in[2];
    const float* ln1_g   = (const float*)d_in[3];
    const float* ln1_b   = (const float*)d_in[4];
    const float* attn_w  = (const float*)d_in[5];
    const float* attn_lA = (const float*)d_in[6];
    const float* attn_lB = (const float*)d_in[7];
    const float* proj_w  = (const float*)d_in[8];
    const float* proj_lA = (const float*)d_in[9];
    const float* proj_lB = (const float*)d_in[10];
    const float* ln2_g   = (const float*)d_in[11];
    const float* ln2_b   = (const float*)d_in[12];
    const float* fc_w    = (const float*)d_in[13];
    const float* fc_b    = (const float*)d_in[14];
    const float* mproj_w = (const float*)d_in[15];
    const float* mproj_b = (const float*)d_in[16];
    const float* lnf_g   = (const float*)d_in[17];
    const float* lnf_b   = (const float*)d_in[18];
    const float* head_w  = (const float*)d_in[19];
    float* out = (float*)d_out;

    float *X, *H, *QKV, *Q, *K, *V, *ATT, *Y, *FC, *TMP;
    cudaGetSymbolAddress((void**)&X,   g_X);
    cudaGetSymbolAddress((void**)&H,   g_H);
    cudaGetSymbolAddress((void**)&QKV, g_QKV);
    cudaGetSymbolAddress((void**)&Q,   g_Q);
    cudaGetSymbolAddress((void**)&K,   g_K);
    cudaGetSymbolAddress((void**)&V,   g_V);
    cudaGetSymbolAddress((void**)&ATT, g_ATT);
    cudaGetSymbolAddress((void**)&Y,   g_Y);
    cudaGetSymbolAddress((void**)&FC,  g_FC);
    cudaGetSymbolAddress((void**)&TMP, g_TMP);

    detect_idx_kernel<<<1, 256>>>((const unsigned int*)idx);
    embed_kernel<<<(MTOK*CDIM + 255)/256, 256>>>(idx, wte, wpe, X);

    const int NB = BSZ * NHEAD;   // 16 attention batches

    for (int l = 0; l < NLAYER; l++) {
        const float* w_qkv = attn_w  + (long long)l * 3*CDIM*CDIM;
        const float* lA_q  = attn_lA + (long long)l * RANK*CDIM;
        const float* lB_q  = attn_lB + (long long)l * 3*CDIM*RANK;
        const float* w_pr  = proj_w  + (long long)l * CDIM*CDIM;
        const float* lA_p  = proj_lA + (long long)l * RANK*CDIM;
        const float* lB_p  = proj_lB + (long long)l * CDIM*RANK;
        const float* w_fc  = fc_w    + (long long)l * 4*CDIM*CDIM;
        const float* b_fc  = fc_b    + (long long)l * 4*CDIM;
        const float* w_mp  = mproj_w + (long long)l * CDIM*4*CDIM;
        const float* b_mp  = mproj_b + (long long)l * CDIM;

        // ---- attention ----
        ln_kernel<<<MTOK, 128>>>(X, ln1_g + l*CDIM, ln1_b + l*CDIM, H);
        lora_xa_kernel<<<MTOK, 256>>>(H, lA_q, TMP);
        gemm_kernel<1><<<gemm_grid(MTOK, 3*CDIM, 1), 256>>>(
            H, w_qkv, nullptr, QKV, MTOK, 3*CDIM, CDIM, 1.0f, 0, 0, 0, 0);
        lora_add_kernel<<<(int)(((long long)MTOK*3*CDIM + 255)/256), 256>>>(QKV, TMP, lB_q, 3*CDIM);
        split_qkv_kernel<<<(BSZ*NHEAD*TLEN*HD + 255)/256, 256>>>(QKV, Q, K, V);

        // scores: ATT[bh] = 0.125 * Q[bh] @ K[bh]^T   (causal block skip)
        gemm_kernel<1><<<gemm_grid(TLEN, TLEN, NB), 256>>>(
            Q, K, nullptr, ATT, TLEN, TLEN, HD, 0.125f,
            (long long)TLEN*HD, (long long)TLEN*HD, (long long)TLEN*TLEN, 1);
        softmax_kernel<<<NB*TLEN, 256>>>(ATT);
        // y_heads = ATT @ V  (reuse Q as output buffer)
        gemm_kernel<0><<<gemm_grid(TLEN, HD, NB), 256>>>(
            ATT, V, nullptr, Q, TLEN, HD, TLEN, 1.0f,
            (long long)TLEN*TLEN, (long long)TLEN*HD, (long long)TLEN*HD, 0);
        merge_y_kernel<<<(MTOK*CDIM + 255)/256, 256>>>(Q, Y);

        lora_xa_kernel<<<MTOK, 256>>>(Y, lA_p, TMP);
        gemm_kernel<1><<<gemm_grid(MTOK, CDIM, 1), 256>>>(
            Y, w_pr, nullptr, H, MTOK, CDIM, CDIM, 1.0f, 0, 0, 0, 0);
        lora_add_kernel<<<(int)(((long long)MTOK*CDIM + 255)/256), 256>>>(H, TMP, lB_p, CDIM);
        add_kernel<<<(MTOK*CDIM + 255)/256, 256>>>(X, H, MTOK*CDIM);

        // ---- MLP ----
        ln_kernel<<<MTOK, 128>>>(X, ln2_g + l*CDIM, ln2_b + l*CDIM, H);
        gemm_kernel<1><<<gemm_grid(MTOK, 4*CDIM, 1), 256>>>(
            H, w_fc, b_fc, FC, MTOK, 4*CDIM, CDIM, 1.0f, 0, 0, 0, 0);
        gelu_kernel<<<(MTOK*4*CDIM + 255)/256, 256>>>(FC, MTOK*4*CDIM);
        gemm_kernel<1><<<gemm_grid(MTOK, CDIM, 1), 256>>>(
            FC, w_mp, b_mp, H, MTOK, CDIM, 4*CDIM, 1.0f, 0, 0, 0, 0);
        add_kernel<<<(MTOK*CDIM + 255)/256, 256>>>(X, H, MTOK*CDIM);
    }

    // ---- final layernorm + vocab head ----
    ln_kernel<<<MTOK, 128>>>(X, lnf_g, lnf_b, H);
    gemm_kernel<1><<<gemm_grid(MTOK, VOCAB, 1), 256>>>(
        H, head_w, nullptr, out, MTOK, VOCAB, CDIM, 1.0f, 0, 0, 0, 0);
}

// round 3
// speedup vs baseline: 2.8247x; 2.8247x over previous
#include <cuda_runtime.h>
#include <cuda_bf16.h>
#include <math.h>

// ---------------------------------------------------------------------------
// GPT_3959959847300 round 3: bf16x3-split GEMMs on mma.sync (HMMA) tensor path.
// (tcgen05 is unavailable: harness PTX target is compute_103, not 103a.)
// B=2, T=1024, C=512, H=8, L=4, V=50257, R=8, lora scale = 4.0
// ---------------------------------------------------------------------------

#define BSZ    2
#define TLEN   1024
#define CDIM   512
#define NHEAD  8
#define HD     64
#define NLAYER 4
#define VOCAB  50257
#define RANK   8
#define LSCALE 4.0f
#define MTOK   (BSZ*TLEN)          // 2048 token rows
#define NBATCH (BSZ*NHEAD)         // 16

// ======================== PTX helpers ========================================
__device__ __forceinline__ unsigned smem_u32(const void* p) {
    unsigned a;
    asm("{ .reg .u64 t; cvta.to.shared.u64 t, %1; cvt.u32.u64 %0, t; }" : "=r"(a) : "l"(p));
    return a;
}
__device__ __forceinline__ void ldmx4(unsigned* r, unsigned addr) {
    asm volatile("ldmatrix.sync.aligned.m8n8.x4.shared.b16 {%0,%1,%2,%3}, [%4];"
                 : "=r"(r[0]), "=r"(r[1]), "=r"(r[2]), "=r"(r[3]) : "r"(addr));
}
__device__ __forceinline__ void mma16816(float* d, const unsigned* a, const unsigned* b) {
    asm volatile(
        "mma.sync.aligned.m16n8k16.row.col.f32.bf16.bf16.f32 "
        "{%0,%1,%2,%3},{%4,%5,%6,%7},{%8,%9},{%0,%1,%2,%3};"
        : "+f"(d[0]), "+f"(d[1]), "+f"(d[2]), "+f"(d[3])
        : "r"(a[0]), "r"(a[1]), "r"(a[2]), "r"(a[3]), "r"(b[0]), "r"(b[1]));
}
__device__ __forceinline__ void cp16(unsigned dst, const void* src, bool pred) {
    int sz = pred ? 16 : 0;
    asm volatile("cp.async.cg.shared.global [%0], [%1], 16, %2;"
                 :: "r"(dst), "l"(src), "r"(sz) : "memory");
}
#define CP_COMMIT()  asm volatile("cp.async.commit_group;" ::: "memory")
#define CP_WAIT_1()  asm volatile("cp.async.wait_group 1;" ::: "memory")
#define CP_WAIT_0()  asm volatile("cp.async.wait_group 0;" ::: "memory")

__device__ __forceinline__ void bsplit(float x, __nv_bfloat16& hi, __nv_bfloat16& lo) {
    hi = __float2bfloat16(x);
    lo = __float2bfloat16(x - __bfloat162float(hi));
}

// ======================== scratch (device globals) ===========================
__device__ float g_X  [MTOK*CDIM];
__device__ float g_H  [MTOK*CDIM];
__device__ float g_QKV[MTOK*3*CDIM];
__device__ float g_ATT[NBATCH*TLEN*TLEN];
__device__ float g_Y  [MTOK*CDIM];
__device__ float g_FC [MTOK*4*CDIM];
__device__ float g_YH [NBATCH*TLEN*HD];
__device__ float g_TMP[MTOK*RANK];
__device__ int   g_idx32;

__device__ __nv_bfloat16 g_wqkv_h[NLAYER*3*CDIM*CDIM], g_wqkv_l[NLAYER*3*CDIM*CDIM];
__device__ __nv_bfloat16 g_wproj_h[NLAYER*CDIM*CDIM],  g_wproj_l[NLAYER*CDIM*CDIM];
__device__ __nv_bfloat16 g_wfc_h [NLAYER*4*CDIM*CDIM], g_wfc_l [NLAYER*4*CDIM*CDIM];
__device__ __nv_bfloat16 g_wmp_h [NLAYER*CDIM*4*CDIM], g_wmp_l [NLAYER*CDIM*4*CDIM];
__device__ __nv_bfloat16 g_whead_h[VOCAB*CDIM],        g_whead_l[VOCAB*CDIM];
__device__ __nv_bfloat16 g_Hh[MTOK*CDIM],  g_Hl[MTOK*CDIM];
__device__ __nv_bfloat16 g_Yhb[MTOK*CDIM], g_Ylb[MTOK*CDIM];
__device__ __nv_bfloat16 g_FCGh[MTOK*4*CDIM], g_FCGl[MTOK*4*CDIM];
__device__ __nv_bfloat16 g_Qh[NBATCH*TLEN*HD], g_Ql[NBATCH*TLEN*HD];
__device__ __nv_bfloat16 g_Kh[NBATCH*TLEN*HD], g_Kl[NBATCH*TLEN*HD];
__device__ __nv_bfloat16 g_Vth[NBATCH*HD*TLEN], g_Vtl[NBATCH*HD*TLEN];
__device__ __nv_bfloat16 g_ATTh[NBATCH*TLEN*TLEN], g_ATTl[NBATCH*TLEN*TLEN];

// ======================== HMMA GEMM ==========================================
// C[M,N] (+bias, *alpha) = (Ah+Al)[M,K] @ (Bh+Bl)[N,K]^T, 3-term bf16 split.
// Block tile 128x128, 8 warps (64x32 each), K chunk 64, cp.async double buffer.
#define TILE_B    16384                  // one 128x64 bf16 tile (128B rows, swizzled)
#define STAGE_B   (4*TILE_B)             // Ah, Al, Bh, Bl
#define GEMM_SMEM (2*STAGE_B)            // 131072 bytes

// swizzled byte offset within a tile
__device__ __forceinline__ unsigned swz(int row, int colB) {
    unsigned o = (unsigned)(row * 128 + colB);
    return o ^ ((unsigned)(row & 7) << 4);
}

__device__ __forceinline__ void stage_load(
    unsigned sbase,
    const __nv_bfloat16* __restrict__ ah, const __nv_bfloat16* __restrict__ al,
    const __nv_bfloat16* __restrict__ bh, const __nv_bfloat16* __restrict__ bl,
    int m0, int n0, int M, int N, int K, int k0, int lr, int lcB)
{
    // A rows
    {
        int gr = m0 + lr; bool ok = (gr < M); int r = ok ? gr : 0;
        const char* pa = (const char*)(ah + (size_t)r * K + k0) + lcB;
        const char* pl = (const char*)(al + (size_t)r * K + k0) + lcB;
        #pragma unroll
        for (int j = 0; j < 4; j++) {
            unsigned o = swz(lr, lcB + 16*j);
            cp16(sbase + o,          pa + 16*j, ok);
            cp16(sbase + TILE_B + o, pl + 16*j, ok);
        }
    }
    // B rows
    {
        int gr = n0 + lr; bool ok = (gr < N); int r = ok ? gr : 0;
        const char* pb = (const char*)(bh + (size_t)r * K + k0) + lcB;
        const char* pl = (const char*)(bl + (size_t)r * K + k0) + lcB;
        #pragma unroll
        for (int j = 0; j < 4; j++) {
            unsigned o = swz(lr, lcB + 16*j);
            cp16(sbase + 2*TILE_B + o, pb + 16*j, ok);
            cp16(sbase + 3*TILE_B + o, pl + 16*j, ok);
        }
    }
}

__global__ __launch_bounds__(256, 1)
void mma_gemm(const __nv_bfloat16* __restrict__ Ah, const __nv_bfloat16* __restrict__ Al,
              const __nv_bfloat16* __restrict__ Bh, const __nv_bfloat16* __restrict__ Bl,
              const float* __restrict__ bias, float* __restrict__ Cm,
              int M, int N, int K, float alpha,
              long long sA, long long sB, long long sC, int causal)
{
    extern __shared__ char smem_raw[];
    const int m0 = blockIdx.x * 128;
    const int n0 = blockIdx.y * 128;
    if (causal && n0 > m0 + 127) return;
    const long long bz = blockIdx.z;
    const __nv_bfloat16* ah = Ah + bz * sA;
    const __nv_bfloat16* al = Al + bz * sA;
    const __nv_bfloat16* bh = Bh + bz * sB;
    const __nv_bfloat16* bl = Bl + bz * sB;
    float* c = Cm + bz * sC;

    const unsigned sbase = smem_u32(smem_raw);
    const int tid  = threadIdx.x;
    const int lane = tid & 31;
    const int wid  = tid >> 5;
    const int wm   = wid & 1;        // 0..1 -> M offset 0/64
    const int wn   = wid >> 1;       // 0..3 -> N offset 0/32/64/96
    const int lr   = tid >> 1;       // loader row 0..127
    const int lcB  = (tid & 1) << 6; // loader byte col 0/64

    float acc[4][4][4];
    #pragma unroll
    for (int i = 0; i < 4; i++)
        #pragma unroll
        for (int j = 0; j < 4; j++)
            #pragma unroll
            for (int t = 0; t < 4; t++) acc[i][j][t] = 0.f;

    const int nc = K >> 6;
    stage_load(sbase, ah, al, bh, bl, m0, n0, M, N, K, 0, lr, lcB);
    CP_COMMIT();

    // ldmatrix per-lane base offsets
    const int a_rin  = lane & 15;          // A: row within 16-tile
    const int a_cB   = (lane >> 4) * 16;   // A: k half (bytes)
    const int b_sel  = lane >> 3;
    const int b_rin  = (b_sel >> 1) * 8 + (lane & 7); // B: row within 16 (two n8 tiles)
    const int b_cB   = (b_sel & 1) * 16;   // B: k half (bytes)

    for (int cI = 0; cI < nc; ++cI) {
        const int s = cI & 1;
        if (cI + 1 < nc) {
            stage_load(sbase + (unsigned)(1 - s) * STAGE_B, ah, al, bh, bl,
                       m0, n0, M, N, K, (cI + 1) << 6, lr, lcB);
            CP_COMMIT();
            CP_WAIT_1();
        } else {
            CP_WAIT_0();
        }
        __syncthreads();

        const unsigned st = sbase + (unsigned)s * STAGE_B;
        #pragma unroll
        for (int ks = 0; ks < 4; ++ks) {
            unsigned ra_h[4][4], ra_l[4][4], rb_h[4][2], rb_l[4][2];
            #pragma unroll
            for (int i = 0; i < 4; ++i) {
                int row = wm*64 + i*16 + a_rin;
                unsigned o = swz(row, ks*32 + a_cB);
                ldmx4(ra_h[i], st + o);
                ldmx4(ra_l[i], st + TILE_B + o);
            }
            #pragma unroll
            for (int jp = 0; jp < 2; ++jp) {
                int row = wn*32 + jp*16 + b_rin;
                unsigned o = swz(row, ks*32 + b_cB);
                unsigned r[4];
                ldmx4(r, st + 2*TILE_B + o);
                rb_h[2*jp][0] = r[0]; rb_h[2*jp][1] = r[1];
                rb_h[2*jp+1][0] = r[2]; rb_h[2*jp+1][1] = r[3];
                ldmx4(r, st + 3*TILE_B + o);
                rb_l[2*jp][0] = r[0]; rb_l[2*jp][1] = r[1];
                rb_l[2*jp+1][0] = r[2]; rb_l[2*jp+1][1] = r[3];
            }
            #pragma unroll
            for (int i = 0; i < 4; ++i)
                #pragma unroll
                for (int j = 0; j < 4; ++j) {
                    mma16816(acc[i][j], ra_h[i], rb_h[j]);
                    mma16816(acc[i][j], ra_l[i], rb_h[j]);
                    mma16816(acc[i][j], ra_h[i], rb_l[j]);
                }
        }
        __syncthreads();
    }

    // ---- epilogue ----
    const int group = lane >> 2, tig = lane & 3;
    #pragma unroll
    for (int i = 0; i < 4; ++i) {
        int m_lo = m0 + wm*64 + i*16 + group;
        #pragma unroll
        for (int j = 0; j < 4; ++j) {
            int nA = n0 + wn*32 + j*8 + tig*2;
            #pragma unroll
            for (int h = 0; h < 2; ++h) {
                int m = m_lo + h*8;
                if (m >= M) continue;
                float v0 = alpha * acc[i][j][h*2 + 0];
                float v1 = alpha * acc[i][j][h*2 + 1];
                float* crow = c + (long long)m * N;
                if (nA < N) {
                    if (bias) v0 += bias[nA];
                    crow[nA] = v0;
                }
                if (nA + 1 < N) {
                    if (bias) v1 += bias[nA + 1];
                    crow[nA + 1] = v1;
                }
            }
        }
    }
}

// ======================== small kernels ======================================
__global__ void detect_idx_kernel(const unsigned int* w) {
    __shared__ unsigned int s;
    if (threadIdx.x == 0) s = 0u;
    __syncthreads();
    unsigned int v = 0u;
    for (int i = threadIdx.x; i < 1024; i += blockDim.x) v |= w[2*i + 1];
    atomicOr(&s, v);
    __syncthreads();
    if (threadIdx.x == 0) g_idx32 = (s != 0u) ? 1 : 0;
}

__global__ void embed_kernel(const void* idx, const float* __restrict__ wte,
                             const float* __restrict__ wpe, float* __restrict__ x) {
    int i = blockIdx.x * blockDim.x + threadIdx.x;
    if (i >= MTOK*CDIM) return;
    int c  = i % CDIM;
    int bt = i / CDIM;
    int t  = bt % TLEN;
    long long tok;
    if (g_idx32) tok = (long long)((const int*)idx)[bt];
    else         tok = ((const long long*)idx)[bt];
    x[i] = wte[tok*CDIM + c] + wpe[(long long)t*CDIM + c];
}

__global__ void ln_split_kernel(const float* __restrict__ x, const float* __restrict__ g,
                                const float* __restrict__ b, float* __restrict__ out,
                                __nv_bfloat16* __restrict__ oh, __nv_bfloat16* __restrict__ ol) {
    const int row = blockIdx.x;
    const float* xr = x + (long long)row * CDIM;
    __shared__ float sx[CDIM];
    __shared__ float red[128];
    __shared__ float s_mean, s_rstd;
    int tid = threadIdx.x;  // 128
    float s = 0.f;
    for (int c = tid; c < CDIM; c += 128) { float v = xr[c]; sx[c] = v; s += v; }
    red[tid] = s; __syncthreads();
    for (int st = 64; st > 0; st >>= 1) { if (tid < st) red[tid] += red[tid+st]; __syncthreads(); }
    if (tid == 0) s_mean = red[0] / (float)CDIM;
    __syncthreads();
    float mean = s_mean;
    float sq = 0.f;
    for (int c = tid; c < CDIM; c += 128) { float d = sx[c] - mean; sq += d*d; }
    red[tid] = sq; __syncthreads();
    for (int st = 64; st > 0; st >>= 1) { if (tid < st) red[tid] += red[tid+st]; __syncthreads(); }
    if (tid == 0) s_rstd = rsqrtf(red[0] / (float)CDIM + 1e-5f);
    __syncthreads();
    float rstd = s_rstd;
    for (int c = tid; c < CDIM; c += 128) {
        float v = (sx[c] - mean) * rstd * g[c] + b[c];
        long long o = (long long)row*CDIM + c;
        out[o] = v;
        __nv_bfloat16 hi, lo; bsplit(v, hi, lo);
        oh[o] = hi; ol[o] = lo;
    }
}

__global__ void wsplit_kernel(const float* __restrict__ w, __nv_bfloat16* __restrict__ h,
                              __nv_bfloat16* __restrict__ l, int n) {
    int i = blockIdx.x * 256 + threadIdx.x;
    if (i >= n) return;
    __nv_bfloat16 hi, lo; bsplit(w[i], hi, lo);
    h[i] = hi; l[i] = lo;
}

__global__ void lora_xa_kernel(const float* __restrict__ h, const float* __restrict__ A,
                               float* __restrict__ tmp) {
    int m = blockIdx.x;
    int w = threadIdx.x >> 5;
    int lane = threadIdx.x & 31;
    const float* hr = h + (long long)m * CDIM;
    const float* Ar = A + (long long)w * CDIM;
    float s = 0.f;
    for (int c = lane; c < CDIM; c += 32) s += hr[c] * Ar[c];
    #pragma unroll
    for (int o = 16; o > 0; o >>= 1) s += __shfl_down_sync(0xffffffffu, s, o);
    if (lane == 0) tmp[m*RANK + w] = s;
}

__global__ void lora_add_kernel(float* __restrict__ out, const float* __restrict__ tmp,
                                const float* __restrict__ Bm, int N) {
    long long i = (long long)blockIdx.x * 256 + threadIdx.x;
    if (i >= (long long)MTOK * N) return;
    int n = (int)(i % N);
    int m = (int)(i / N);
    const float* t = tmp + m*RANK;
    const float* b = Bm + (long long)n*RANK;
    float s = 0.f;
    #pragma unroll
    for (int r = 0; r < RANK; r++) s += t[r] * b[r];
    out[i] += LSCALE * s;
}

__global__ void split_qkv_tr_kernel(const float* __restrict__ qkv,
                                    __nv_bfloat16* __restrict__ qh, __nv_bfloat16* __restrict__ ql,
                                    __nv_bfloat16* __restrict__ kh, __nv_bfloat16* __restrict__ kl,
                                    __nv_bfloat16* __restrict__ vth, __nv_bfloat16* __restrict__ vtl) {
    int i = blockIdx.x * 256 + threadIdx.x;
    if (i >= NBATCH*TLEN*HD) return;
    int d = i % HD;
    int t = (i / HD) % TLEN;
    int h = (i / (HD*TLEN)) % NHEAD;
    int b = i / (HD*TLEN*NHEAD);
    long long src = (long long)(b*TLEN + t) * (3*CDIM) + h*HD + d;
    __nv_bfloat16 hi, lo;
    bsplit(qkv[src],          hi, lo); qh[i] = hi; ql[i] = lo;
    bsplit(qkv[src + CDIM],   hi, lo); kh[i] = hi; kl[i] = lo;
    long long vi = ((long long)(b*NHEAD + h) * HD + d) * TLEN + t;
    bsplit(qkv[src + 2*CDIM], hi, lo); vth[vi] = hi; vtl[vi] = lo;
}

__global__ void softmax_split_kernel(const float* __restrict__ att,
                                     __nv_bfloat16* __restrict__ ph,
                                     __nv_bfloat16* __restrict__ pl) {
    int row = blockIdx.x;
    int q = row & (TLEN - 1);
    const float* a = att + (long long)row * TLEN;
    __nv_bfloat16* oh = ph + (long long)row * TLEN;
    __nv_bfloat16* ol = pl + (long long)row * TLEN;
    __shared__ float red[256];
    int tid = threadIdx.x;
    float mx = -1e30f;
    for (int k = tid; k <= q; k += 256) mx = fmaxf(mx, a[k]);
    red[tid] = mx; __syncthreads();
    for (int s = 128; s > 0; s >>= 1) { if (tid < s) red[tid] = fmaxf(red[tid], red[tid+s]); __syncthreads(); }
    mx = red[0]; __syncthreads();
    float sum = 0.f;
    for (int k = tid; k <= q; k += 256) sum += expf(a[k] - mx);
    red[tid] = sum; __syncthreads();
    for (int s = 128; s > 0; s >>= 1) { if (tid < s) red[tid] += red[tid+s]; __syncthreads(); }
    float inv = 1.f / red[0];
    for (int k = tid; k <= q; k += 256) {
        float p = expf(a[k] - mx) * inv;
        __nv_bfloat16 hi, lo; bsplit(p, hi, lo);
        oh[k] = hi; ol[k] = lo;
    }
    __nv_bfloat16 z = __float2bfloat16(0.f);
    for (int k = q + 1 + tid; k < TLEN; k += 256) { oh[k] = z; ol[k] = z; }
}

__global__ void merge_y_split_kernel(const float* __restrict__ yh, float* __restrict__ y,
                                     __nv_bfloat16* __restrict__ oh, __nv_bfloat16* __restrict__ ol) {
    int i = blockIdx.x * 256 + threadIdx.x;
    if (i >= MTOK*CDIM) return;
    int c = i % CDIM;
    int t = (i / CDIM) % TLEN;
    int b = i / (CDIM*TLEN);
    int h = c / HD, d = c % HD;
    float v = yh[(((long long)(b*NHEAD + h) * TLEN) + t) * HD + d];
    y[i] = v;
    __nv_bfloat16 hi, lo; bsplit(v, hi, lo);
    oh[i] = hi; ol[i] = lo;
}

__global__ void gelu_split_kernel(const float* __restrict__ x,
                                  __nv_bfloat16* __restrict__ oh, __nv_bfloat16* __restrict__ ol) {
    int i = blockIdx.x * 256 + threadIdx.x;
    if (i >= MTOK*4*CDIM) return;
    float v = x[i];
    float gv = 0.5f * v * (1.f + tanhf(0.7978845608028654f * (v + 0.044715f * v*v*v)));
    __nv_bfloat16 hi, lo; bsplit(gv, hi, lo);
    oh[i] = hi; ol[i] = lo;
}

__global__ void add_kernel(float* __restrict__ x, const float* __restrict__ y, int n) {
    int i = blockIdx.x * 256 + threadIdx.x;
    if (i < n) x[i] += y[i];
}

// ======================== host driver ========================================
extern "C" void kernel_launch(void* const* d_in, const int* in_sizes, int n_in,
                              void* d_out, int out_size) {
    (void)in_sizes; (void)n_in; (void)out_size;
    const void*  idx     = d_in[0];
    const float* wte     = (const float*)d_in[1];
    const float* wpe     = (const float*)d_in[2];
    const float* ln1_g   = (const float*)d_in[3];
    const float* ln1_b   = (const float*)d_in[4];
    const float* attn_w  = (const float*)d_in[5];
    const float* attn_lA = (const float*)d_in[6];
    const float* attn_lB = (const float*)d_in[7];
    const float* proj_w  = (const float*)d_in[8];
    const float* proj_lA = (const float*)d_in[9];
    const float* proj_lB = (const float*)d_in[10];
    const float* ln2_g   = (const float*)d_in[11];
    const float* ln2_b   = (const float*)d_in[12];
    const float* fc_w    = (const float*)d_in[13];
    const float* fc_b    = (const float*)d_in[14];
    const float* mproj_w = (const float*)d_in[15];
    const float* mproj_b = (const float*)d_in[16];
    const float* lnf_g   = (const float*)d_in[17];
    const float* lnf_b   = (const float*)d_in[18];
    const float* head_w  = (const float*)d_in[19];
    float* out = (float*)d_out;

    float *X, *H, *QKV, *ATT, *Y, *FC, *YH, *TMP;
    cudaGetSymbolAddress((void**)&X,   g_X);
    cudaGetSymbolAddress((void**)&H,   g_H);
    cudaGetSymbolAddress((void**)&QKV, g_QKV);
    cudaGetSymbolAddress((void**)&ATT, g_ATT);
    cudaGetSymbolAddress((void**)&Y,   g_Y);
    cudaGetSymbolAddress((void**)&FC,  g_FC);
    cudaGetSymbolAddress((void**)&YH,  g_YH);
    cudaGetSymbolAddress((void**)&TMP, g_TMP);

    __nv_bfloat16 *wqkv_h, *wqkv_l, *wproj_h, *wproj_l, *wfc_h, *wfc_l, *wmp_h, *wmp_l,
                  *whead_h, *whead_l, *Hh, *Hl, *Yh, *Yl, *FCGh, *FCGl,
                  *Qh, *Ql, *Kh, *Kl, *Vth, *Vtl, *ATTh, *ATTl;
    cudaGetSymbolAddress((void**)&wqkv_h,  g_wqkv_h);  cudaGetSymbolAddress((void**)&wqkv_l,  g_wqkv_l);
    cudaGetSymbolAddress((void**)&wproj_h, g_wproj_h); cudaGetSymbolAddress((void**)&wproj_l, g_wproj_l);
    cudaGetSymbolAddress((void**)&wfc_h,   g_wfc_h);   cudaGetSymbolAddress((void**)&wfc_l,   g_wfc_l);
    cudaGetSymbolAddress((void**)&wmp_h,   g_wmp_h);   cudaGetSymbolAddress((void**)&wmp_l,   g_wmp_l);
    cudaGetSymbolAddress((void**)&whead_h, g_whead_h); cudaGetSymbolAddress((void**)&whead_l, g_whead_l);
    cudaGetSymbolAddress((void**)&Hh,   g_Hh);   cudaGetSymbolAddress((void**)&Hl,   g_Hl);
    cudaGetSymbolAddress((void**)&Yh,   g_Yhb);  cudaGetSymbolAddress((void**)&Yl,   g_Ylb);
    cudaGetSymbolAddress((void**)&FCGh, g_FCGh); cudaGetSymbolAddress((void**)&FCGl, g_FCGl);
    cudaGetSymbolAddress((void**)&Qh,   g_Qh);   cudaGetSymbolAddress((void**)&Ql,   g_Ql);
    cudaGetSymbolAddress((void**)&Kh,   g_Kh);   cudaGetSymbolAddress((void**)&Kl,   g_Kl);
    cudaGetSymbolAddress((void**)&Vth,  g_Vth);  cudaGetSymbolAddress((void**)&Vtl,  g_Vtl);
    cudaGetSymbolAddress((void**)&ATTh, g_ATTh); cudaGetSymbolAddress((void**)&ATTl, g_ATTl);

    cudaFuncSetAttribute(mma_gemm, cudaFuncAttributeMaxDynamicSharedMemorySize, GEMM_SMEM);

    detect_idx_kernel<<<1, 256>>>((const unsigned int*)idx);
    embed_kernel<<<(MTOK*CDIM + 255)/256, 256>>>(idx, wte, wpe, X);

    // ---- weight splits ----
    {
        int n;
        n = NLAYER*3*CDIM*CDIM; wsplit_kernel<<<(n+255)/256, 256>>>(attn_w,  wqkv_h,  wqkv_l,  n);
        n = NLAYER*CDIM*CDIM;   wsplit_kernel<<<(n+255)/256, 256>>>(proj_w,  wproj_h, wproj_l, n);
        n = NLAYER*4*CDIM*CDIM; wsplit_kernel<<<(n+255)/256, 256>>>(fc_w,    wfc_h,   wfc_l,   n);
        n = NLAYER*CDIM*4*CDIM; wsplit_kernel<<<(n+255)/256, 256>>>(mproj_w, wmp_h,   wmp_l,   n);
        n = VOCAB*CDIM;         wsplit_kernel<<<(n+255)/256, 256>>>(head_w,  whead_h, whead_l, n);
    }

    for (int l = 0; l < NLAYER; l++) {
        long long oq = (long long)l * 3*CDIM*CDIM;
        long long op = (long long)l * CDIM*CDIM;
        long long of = (long long)l * 4*CDIM*CDIM;
        long long om = (long long)l * CDIM*4*CDIM;
        const float* lA_q = attn_lA + (long long)l * RANK*CDIM;
        const float* lB_q = attn_lB + (long long)l * 3*CDIM*RANK;
        const float* lA_p = proj_lA + (long long)l * RANK*CDIM;
        const float* lB_p = proj_lB + (long long)l * CDIM*RANK;

        // ---- attention ----
        ln_split_kernel<<<MTOK, 128>>>(X, ln1_g + l*CDIM, ln1_b + l*CDIM, H, Hh, Hl);
        lora_xa_kernel<<<MTOK, 256>>>(H, lA_q, TMP);
        mma_gemm<<<dim3(MTOK/128, 3*CDIM/128, 1), 256, GEMM_SMEM>>>(
            Hh, Hl, wqkv_h + oq, wqkv_l + oq, nullptr, QKV,
            MTOK, 3*CDIM, CDIM, 1.0f, 0, 0, 0, 0);
        lora_add_kernel<<<(int)(((long long)MTOK*3*CDIM + 255)/256), 256>>>(QKV, TMP, lB_q, 3*CDIM);
        split_qkv_tr_kernel<<<(NBATCH*TLEN*HD + 255)/256, 256>>>(QKV, Qh, Ql, Kh, Kl, Vth, Vtl);

        mma_gemm<<<dim3(TLEN/128, TLEN/128, NBATCH), 256, GEMM_SMEM>>>(
            Qh, Ql, Kh, Kl, nullptr, ATT,
            TLEN, TLEN, HD, 0.125f,
            (long long)TLEN*HD, (long long)TLEN*HD, (long long)TLEN*TLEN, 1);
        softmax_split_kernel<<<NBATCH*TLEN, 256>>>(ATT, ATTh, ATTl);
        mma_gemm<<<dim3(TLEN/128, 1, NBATCH), 256, GEMM_SMEM>>>(
            ATTh, ATTl, Vth, Vtl, nullptr, YH,
            TLEN, HD, TLEN, 1.0f,
            (long long)TLEN*TLEN, (long long)HD*TLEN, (long long)TLEN*HD, 0);
        merge_y_split_kernel<<<(MTOK*CDIM + 255)/256, 256>>>(YH, Y, Yh, Yl);

        lora_xa_kernel<<<MTOK, 256>>>(Y, lA_p, TMP);
        mma_gemm<<<dim3(MTOK/128, CDIM/128, 1), 256, GEMM_SMEM>>>(
            Yh, Yl, wproj_h + op, wproj_l + op, nullptr, H,
            MTOK, CDIM, CDIM, 1.0f, 0, 0, 0, 0);
        lora_add_kernel<<<(int)(((long long)MTOK*CDIM + 255)/256), 256>>>(H, TMP, lB_p, CDIM);
        add_kernel<<<(MTOK*CDIM + 255)/256, 256>>>(X, H, MTOK*CDIM);

        // ---- MLP ----
        ln_split_kernel<<<MTOK, 128>>>(X, ln2_g + l*CDIM, ln2_b + l*CDIM, H, Hh, Hl);
        mma_gemm<<<dim3(MTOK/128, 4*CDIM/128, 1), 256, GEMM_SMEM>>>(
            Hh, Hl, wfc_h + of, wfc_l + of, fc_b + (long long)l*4*CDIM, FC,
            MTOK, 4*CDIM, CDIM, 1.0f, 0, 0, 0, 0);
        gelu_split_kernel<<<(MTOK*4*CDIM + 255)/256, 256>>>(FC, FCGh, FCGl);
        mma_gemm<<<dim3(MTOK/128, CDIM/128, 1), 256, GEMM_SMEM>>>(
            FCGh, FCGl, wmp_h + om, wmp_l + om, mproj_b + (long long)l*CDIM, H,
            MTOK, CDIM, 4*CDIM, 1.0f, 0, 0, 0, 0);
        add_kernel<<<(MTOK*CDIM + 255)/256, 256>>>(X, H, MTOK*CDIM);
    }

    // ---- final layernorm + vocab head ----
    ln_split_kernel<<<MTOK, 128>>>(X, lnf_g, lnf_b, H, Hh, Hl);
    mma_gemm<<<dim3(MTOK/128, (VOCAB + 127)/128, 1), 256, GEMM_SMEM>>>(
        Hh, Hl, whead_h, whead_l, nullptr, out,
        MTOK, VOCAB, CDIM, 1.0f, 0, 0, 0, 0);
}